// round 7
// baseline (speedup 1.0000x reference)
#include <cuda_runtime.h>
#include <cuda_bf16.h>

#define N_NODES_MAX 1000000
#define KE_HALF 7.199822675975274f   // 14.399645351950548 / 2

// Per-node z value (index_to_z[species[i]], 1..100 fits in u8). 1 MB.
__device__ unsigned char g_z[N_NODES_MAX];
// a0*d..a3*d, c0..c3 (normalized), p
__device__ float g_params[9];

__device__ __forceinline__ float softplus_f(float x) {
    return log1pf(expf(x));
}

__global__ void prep_kernel(const int* __restrict__ species,
                            const int* __restrict__ index_to_z,
                            const float* __restrict__ a_raw,
                            const float* __restrict__ c_raw,
                            const float* __restrict__ p_raw,
                            const float* __restrict__ d_raw,
                            float* __restrict__ out,
                            int n_nodes) {
    int i = blockIdx.x * blockDim.x + threadIdx.x;

    if (i < 9) {
        float d = softplus_f(d_raw[0]);
        if (i < 4) {
            g_params[i] = softplus_f(a_raw[i]) * d;     // fold d into a_k
        } else if (i < 8) {
            float c0 = softplus_f(c_raw[0]);
            float c1 = softplus_f(c_raw[1]);
            float c2 = softplus_f(c_raw[2]);
            float c3 = softplus_f(c_raw[3]);
            float inv_s = 1.0f / (c0 + c1 + c2 + c3);
            g_params[i] = softplus_f(c_raw[i - 4]) * inv_s;
        } else {
            g_params[8] = softplus_f(p_raw[0]);         // p
        }
    }

    if (i < n_nodes) {
        out[i] = 0.0f;  // zero-init accumulator (harness poisons d_out)
        g_z[i] = (unsigned char)index_to_z[species[i]];
    }
}

// Full per-edge energy from z values (all math, no memory).
__device__ __forceinline__ float edge_compute(float dd, float cc,
                                              float zi, float zj,
                                              float a0, float a1, float a2, float a3,
                                              float c0, float c1, float c2, float c3,
                                              float p) {
    float zpi = __expf(p * __logf(zi));   // z >= 1 so log safe
    float zpj = __expf(p * __logf(zj));

    float x = __fdividef(KE_HALF * cc * zi * zj, dd + 1e-8f);

    float t = dd * (zpi + zpj);           // a_k pre-scaled by d

    float y = c0 * __expf(-a0 * t)
            + c1 * __expf(-a1 * t)
            + c2 * __expf(-a2 * t)
            + c3 * __expf(-a3 * t);

    float sd = dd * (1.0f / 1.5f);
    float s1 = 1.0f - sd;
    sd = fmaxf(sd, 1e-8f);
    s1 = fmaxf(s1, 1e-8f);
    float e = __expf(__fdividef(1.0f, s1) - __fdividef(1.0f, sd));
    float w = __fdividef(1.0f, 1.0f + e);

    return w * x * y;
}

// L1-bypassing vector loads: streams never allocate in L1.
__device__ __forceinline__ float4 ldcv_f4(const float4* p) {
    float4 v;
    asm volatile("ld.global.cv.v4.f32 {%0,%1,%2,%3}, [%4];"
                 : "=f"(v.x), "=f"(v.y), "=f"(v.z), "=f"(v.w) : "l"(p));
    return v;
}
__device__ __forceinline__ int4 ldcv_i4(const int4* p) {
    int4 v;
    asm volatile("ld.global.cv.v4.b32 {%0,%1,%2,%3}, [%4];"
                 : "=r"(v.x), "=r"(v.y), "=r"(v.z), "=r"(v.w) : "l"(p));
    return v;
}

__global__ __launch_bounds__(256)
void edge_kernel(const float4* __restrict__ dist4,
                 const float4* __restrict__ cut4,
                 const int4* __restrict__ snd4,
                 const int4* __restrict__ rcv4,
                 float* __restrict__ out,
                 int n8, int n_tail_base, int n_edges) {
    int i = blockIdx.x * blockDim.x + threadIdx.x;

    float a0 = g_params[0], a1 = g_params[1], a2 = g_params[2], a3 = g_params[3];
    float c0 = g_params[4], c1 = g_params[5], c2 = g_params[6], c3 = g_params[7];
    float p  = g_params[8];

    if (i < n8) {
        int ia = i;          // edges block A (float4 slot)
        int ib = i + n8;     // edges block B (float4 slot) — both fully coalesced

        // 8 stream loads (L1-bypass)
        float4 dvA = ldcv_f4(&dist4[ia]);
        float4 dvB = ldcv_f4(&dist4[ib]);
        float4 cvA = ldcv_f4(&cut4[ia]);
        float4 cvB = ldcv_f4(&cut4[ib]);
        int4   svA = ldcv_i4(&snd4[ia]);
        int4   svB = ldcv_i4(&snd4[ib]);
        int4   rvA = ldcv_i4(&rcv4[ia]);
        int4   rvB = ldcv_i4(&rcv4[ib]);

        // 16 random gathers issued back-to-back: ~24 outstanding ops/warp
        float zjA0 = (float)g_z[svA.x];
        float zjA1 = (float)g_z[svA.y];
        float zjA2 = (float)g_z[svA.z];
        float zjA3 = (float)g_z[svA.w];
        float zjB0 = (float)g_z[svB.x];
        float zjB1 = (float)g_z[svB.y];
        float zjB2 = (float)g_z[svB.z];
        float zjB3 = (float)g_z[svB.w];
        float ziA0 = (float)g_z[rvA.x];
        float ziA1 = (float)g_z[rvA.y];
        float ziA2 = (float)g_z[rvA.z];
        float ziA3 = (float)g_z[rvA.w];
        float ziB0 = (float)g_z[rvB.x];
        float ziB1 = (float)g_z[rvB.y];
        float ziB2 = (float)g_z[rvB.z];
        float ziB3 = (float)g_z[rvB.w];

        float eA0 = edge_compute(dvA.x, cvA.x, ziA0, zjA0, a0,a1,a2,a3, c0,c1,c2,c3, p);
        float eA1 = edge_compute(dvA.y, cvA.y, ziA1, zjA1, a0,a1,a2,a3, c0,c1,c2,c3, p);
        float eA2 = edge_compute(dvA.z, cvA.z, ziA2, zjA2, a0,a1,a2,a3, c0,c1,c2,c3, p);
        float eA3 = edge_compute(dvA.w, cvA.w, ziA3, zjA3, a0,a1,a2,a3, c0,c1,c2,c3, p);
        float eB0 = edge_compute(dvB.x, cvB.x, ziB0, zjB0, a0,a1,a2,a3, c0,c1,c2,c3, p);
        float eB1 = edge_compute(dvB.y, cvB.y, ziB1, zjB1, a0,a1,a2,a3, c0,c1,c2,c3, p);
        float eB2 = edge_compute(dvB.z, cvB.z, ziB2, zjB2, a0,a1,a2,a3, c0,c1,c2,c3, p);
        float eB3 = edge_compute(dvB.w, cvB.w, ziB3, zjB3, a0,a1,a2,a3, c0,c1,c2,c3, p);

        // grouped scatters (RED, no return)
        atomicAdd(&out[rvA.x], eA0);
        atomicAdd(&out[rvA.y], eA1);
        atomicAdd(&out[rvA.z], eA2);
        atomicAdd(&out[rvA.w], eA3);
        atomicAdd(&out[rvB.x], eB0);
        atomicAdd(&out[rvB.y], eB1);
        atomicAdd(&out[rvB.z], eB2);
        atomicAdd(&out[rvB.w], eB3);
    }

    // tail (n_edges % 8): distribute over first warp
    {
        int t = n_tail_base + i;
        if (t < n_edges && i < 32) {
            const float* dist = (const float*)dist4;
            const float* cut  = (const float*)cut4;
            const int*   snd  = (const int*)snd4;
            const int*   rcv  = (const int*)rcv4;
            float zi = (float)g_z[rcv[t]];
            float zj = (float)g_z[snd[t]];
            float en = edge_compute(dist[t], cut[t], zi, zj, a0,a1,a2,a3, c0,c1,c2,c3, p);
            atomicAdd(&out[rcv[t]], en);
        }
    }
}

extern "C" void kernel_launch(void* const* d_in, const int* in_sizes, int n_in,
                              void* d_out, int out_size) {
    const int*   node_species = (const int*)d_in[0];
    const float* distances    = (const float*)d_in[1];
    const float* cutoffs      = (const float*)d_in[2];
    const int*   senders      = (const int*)d_in[3];
    const int*   receivers    = (const int*)d_in[4];
    const int*   index_to_z   = (const int*)d_in[5];
    const float* a_raw        = (const float*)d_in[6];
    const float* c_raw        = (const float*)d_in[7];
    const float* p_raw        = (const float*)d_in[8];
    const float* d_raw        = (const float*)d_in[9];
    float* out = (float*)d_out;

    int n_nodes = in_sizes[0];
    int n_edges = in_sizes[1];

    {
        int threads = 256;
        int blocks = (n_nodes + threads - 1) / threads;
        prep_kernel<<<blocks, threads>>>(node_species, index_to_z,
                                         a_raw, c_raw, p_raw, d_raw,
                                         out, n_nodes);
    }
    {
        int n8 = n_edges >> 3;                 // pairs of float4 slots
        int threads = 256;
        int blocks = (n8 + threads - 1) / threads;
        if (blocks == 0) blocks = 1;
        edge_kernel<<<blocks, threads>>>((const float4*)distances,
                                         (const float4*)cutoffs,
                                         (const int4*)senders,
                                         (const int4*)receivers,
                                         out, n8, n8 << 3, n_edges);
    }
}